// round 7
// baseline (speedup 1.0000x reference)
#include <cuda_runtime.h>
#include <cuda_fp16.h>
#include <math.h>

#define BATCH 4
#define SEQ 2048
#define DMODEL 256
#define NHEAD 8
#define DHEAD 32
#define NLAYER 4
#define ROWS (BATCH*SEQ)   // 8192

// ---------------- scratch ----------------
__device__ float g_h   [ROWS*DMODEL];
__device__ float g_qkv [ROWS*3*DMODEL];
__device__ float g_attn[ROWS*DMODEL];
__device__ float g_ffn [ROWS*2*DMODEL];
__device__ float g_cs  [ROWS*32];
__device__ float g_Wf  [NLAYER*DMODEL*DMODEL];
__device__ float g_bf  [NLAYER*DMODEL];

// ---------------- helpers ----------------
__device__ __forceinline__ unsigned ph2(float a, float b) {
    __half2 h = __floats2half2_rn(a, b);
    return *reinterpret_cast<unsigned*>(&h);
}

__device__ __forceinline__ float ex2(float x) {
    float y; asm("ex2.approx.ftz.f32 %0, %1;" : "=f"(y) : "f"(x)); return y;
}

__device__ __forceinline__ void mma_h(float* d, const unsigned* a, unsigned b0, unsigned b1) {
    asm("mma.sync.aligned.m16n8k16.row.col.f32.f16.f16.f32 "
        "{%0,%1,%2,%3},{%4,%5,%6,%7},{%8,%9},{%0,%1,%2,%3};"
        : "+f"(d[0]), "+f"(d[1]), "+f"(d[2]), "+f"(d[3])
        : "r"(a[0]), "r"(a[1]), "r"(a[2]), "r"(a[3]), "r"(b0), "r"(b1));
}

__device__ __forceinline__ void ldsm4t(unsigned* r, const void* p) {
    unsigned a = (unsigned)__cvta_generic_to_shared(p);
    asm volatile("ldmatrix.sync.aligned.m8n8.x4.trans.shared.b16 {%0,%1,%2,%3}, [%4];"
        : "=r"(r[0]), "=r"(r[1]), "=r"(r[2]), "=r"(r[3]) : "r"(a));
}

// ---------------- small setup kernels ----------------
__global__ void proj_kernel(const float* __restrict__ hin, const float* __restrict__ pw,
                            const float* __restrict__ pb, float* __restrict__ hout) {
    int idx = blockIdx.x*256 + threadIdx.x;       // ROWS*64
    int row = idx >> 6, c4 = idx & 63;
    float4 w = ((const float4*)pw)[c4];
    float4 b = ((const float4*)pb)[c4];
    float hv = hin[row];
    float4 r; r.x = hv*w.x + b.x; r.y = hv*w.y + b.y; r.z = hv*w.z + b.z; r.w = hv*w.w + b.w;
    ((float4*)hout)[row*64 + c4] = r;
}

__global__ void freqs_kernel(const float* __restrict__ pos, float* __restrict__ cs) {
    int idx = blockIdx.x*blockDim.x + threadIdx.x;   // ROWS*16
    int row = idx >> 4; int r = idx & 15; int axis = r >> 3; int fi = r & 7;
    float coord = pos[row*2 + axis];
    float inv = powf(10000.f, -(float)fi * 0.125f);
    float ang = coord * 64.f * inv;
    float s, c; sincosf(ang, &s, &c);
    cs[row*32 + axis*16 + fi]     = c;
    cs[row*32 + axis*16 + 8 + fi] = s;
}

__global__ void fuse_bias_kernel(const float* __restrict__ out_b, const float* __restrict__ O_w,
                                 const float* __restrict__ O_b, float* __restrict__ bf) {
    int l = blockIdx.x, j = threadIdx.x;
    const float* wb = O_w + (size_t)l*DMODEL*DMODEL;
    const float* ob = out_b + l*DMODEL;
    float acc = O_b[l*DMODEL + j];
    for (int i = 0; i < DMODEL; i++) acc = fmaf(ob[i], wb[i*DMODEL + j], acc);
    bf[l*DMODEL + j] = acc;
}

// ---------------- fp16 GEMM (generic): C[M,N] = A[M,K] @ W[K,N] (+bias)(+relu), batched via z ----------------
template<int MT, int HASB, int RELU>
__global__ void __launch_bounds__(256) gemm_h(const float* __restrict__ A, const float* __restrict__ W,
                                              const float* __restrict__ bias, float* __restrict__ C,
                                              int M, int K, int N, int sA, int sW, int sC) {
    __shared__ unsigned As2[2][MT*32*20];
    __shared__ __half  Bsh[2][32*136];
    A += (size_t)blockIdx.z*sA; W += (size_t)blockIdx.z*sW; C += (size_t)blockIdx.z*sC;
    const int BM = MT*32;
    int bm = blockIdx.y*BM, bn = blockIdx.x*128;
    int tid = threadIdx.x, lane = tid & 31, warp = tid >> 5;
    int q = lane >> 2, t = lane & 3;
    int wm = (warp >> 2)*(16*MT), wn = (warp & 3)*32;
    float acc[MT][4][4];
#pragma unroll
    for (int a = 0; a < MT; a++)
#pragma unroll
        for (int b = 0; b < 4; b++)
#pragma unroll
            for (int c = 0; c < 4; c++) acc[a][b][c] = 0.f;

    int arow, acolf;
    if (MT == 4) { arow = tid >> 1; acolf = (tid & 1)*16; }
    else         { arow = tid >> 2; acolf = (tid & 3)*8; }
    int brow = tid >> 4, bcol = (tid & 15)*8;
    const float* Ap = A + (size_t)(bm + arow)*K + acolf;
    const float* Wp = W + (size_t)brow*N + bn + bcol;

    float4 ra[4], rb[4];
    ra[0] = *(const float4*)(Ap);
    ra[1] = *(const float4*)(Ap + 4);
    if (MT == 4) { ra[2] = *(const float4*)(Ap + 8); ra[3] = *(const float4*)(Ap + 12); }
    rb[0] = *(const float4*)(Wp);
    rb[1] = *(const float4*)(Wp + 4);
    rb[2] = *(const float4*)(Wp + (size_t)16*N);
    rb[3] = *(const float4*)(Wp + (size_t)16*N + 4);
    {
        *(uint4*)&As2[0][arow*20 + acolf/2] =
            make_uint4(ph2(ra[0].x,ra[0].y), ph2(ra[0].z,ra[0].w), ph2(ra[1].x,ra[1].y), ph2(ra[1].z,ra[1].w));
        if (MT == 4)
            *(uint4*)&As2[0][arow*20 + acolf/2 + 4] =
                make_uint4(ph2(ra[2].x,ra[2].y), ph2(ra[2].z,ra[2].w), ph2(ra[3].x,ra[3].y), ph2(ra[3].z,ra[3].w));
        *(uint4*)&Bsh[0][brow*136 + bcol] =
            make_uint4(ph2(rb[0].x,rb[0].y), ph2(rb[0].z,rb[0].w), ph2(rb[1].x,rb[1].y), ph2(rb[1].z,rb[1].w));
        *(uint4*)&Bsh[0][(brow+16)*136 + bcol] =
            make_uint4(ph2(rb[2].x,rb[2].y), ph2(rb[2].z,rb[2].w), ph2(rb[3].x,rb[3].y), ph2(rb[3].z,rb[3].w));
    }
    __syncthreads();

    int buf = 0;
    for (int k0 = 0; k0 < K; k0 += 32) {
        bool more = (k0 + 32) < K;
        if (more) {
            ra[0] = *(const float4*)(Ap + k0 + 32);
            ra[1] = *(const float4*)(Ap + k0 + 36);
            if (MT == 4) { ra[2] = *(const float4*)(Ap + k0 + 40); ra[3] = *(const float4*)(Ap + k0 + 44); }
            rb[0] = *(const float4*)(Wp + (size_t)(k0+32)*N);
            rb[1] = *(const float4*)(Wp + (size_t)(k0+32)*N + 4);
            rb[2] = *(const float4*)(Wp + (size_t)(k0+48)*N);
            rb[3] = *(const float4*)(Wp + (size_t)(k0+48)*N + 4);
        }
#pragma unroll
        for (int ks = 0; ks < 2; ks++) {
            unsigned af[MT][4];
#pragma unroll
            for (int mt = 0; mt < MT; mt++) {
                int r = wm + mt*16 + q;
                af[mt][0] = As2[buf][r*20 + ks*8 + t];
                af[mt][1] = As2[buf][(r+8)*20 + ks*8 + t];
                af[mt][2] = As2[buf][r*20 + ks*8 + t + 4];
                af[mt][3] = As2[buf][(r+8)*20 + ks*8 + t + 4];
            }
#pragma unroll
            for (int ntp = 0; ntp < 2; ntp++) {
                unsigned bb[4];
                ldsm4t(bb, &Bsh[buf][(ks*16 + (lane & 15))*136 + wn + ntp*16 + (lane >> 4)*8]);
#pragma unroll
                for (int mt = 0; mt < MT; mt++) {
                    mma_h(acc[mt][2*ntp],   af[mt], bb[0], bb[1]);
                    mma_h(acc[mt][2*ntp+1], af[mt], bb[2], bb[3]);
                }
            }
        }
        if (more) {
            int nb = buf ^ 1;
            *(uint4*)&As2[nb][arow*20 + acolf/2] =
                make_uint4(ph2(ra[0].x,ra[0].y), ph2(ra[0].z,ra[0].w), ph2(ra[1].x,ra[1].y), ph2(ra[1].z,ra[1].w));
            if (MT == 4)
                *(uint4*)&As2[nb][arow*20 + acolf/2 + 4] =
                    make_uint4(ph2(ra[2].x,ra[2].y), ph2(ra[2].z,ra[2].w), ph2(ra[3].x,ra[3].y), ph2(ra[3].z,ra[3].w));
            *(uint4*)&Bsh[nb][brow*136 + bcol] =
                make_uint4(ph2(rb[0].x,rb[0].y), ph2(rb[0].z,rb[0].w), ph2(rb[1].x,rb[1].y), ph2(rb[1].z,rb[1].w));
            *(uint4*)&Bsh[nb][(brow+16)*136 + bcol] =
                make_uint4(ph2(rb[2].x,rb[2].y), ph2(rb[2].z,rb[2].w), ph2(rb[3].x,rb[3].y), ph2(rb[3].z,rb[3].w));
        }
        __syncthreads();
        buf ^= 1;
    }

#pragma unroll
    for (int mt = 0; mt < MT; mt++) {
        int r0 = bm + wm + mt*16 + q;
#pragma unroll
        for (int nt = 0; nt < 4; nt++) {
            int c0 = bn + wn + nt*8 + 2*t;
            float b0 = 0.f, b1 = 0.f;
            if (HASB) { b0 = bias[c0]; b1 = bias[c0+1]; }
            float v0 = acc[mt][nt][0] + b0, v1 = acc[mt][nt][1] + b1;
            float v2 = acc[mt][nt][2] + b0, v3 = acc[mt][nt][3] + b1;
            if (RELU) { v0=fmaxf(v0,0.f); v1=fmaxf(v1,0.f); v2=fmaxf(v2,0.f); v3=fmaxf(v3,0.f); }
            float2 w0; w0.x = v0; w0.y = v1;
            float2 w1; w1.x = v2; w1.y = v3;
            *(float2*)&C[(size_t)r0*N + c0]     = w0;
            *(float2*)&C[(size_t)(r0+8)*N + c0] = w1;
        }
    }
}

// ---------------- fused GEMM + bias + residual + layernorm ----------------
// C = LN(h + A@W + bias); h updated in place. BM=32, BN=256 (full row), BK=32.
// 8 warps each own 32 cols. Epilogue stages C-tile in smem (unioned over mainloop bufs).
__global__ void __launch_bounds__(256) gemm_ln(const float* __restrict__ A, const float* __restrict__ W,
                                               const float* __restrict__ bias,
                                               const float* __restrict__ g, const float* __restrict__ bb,
                                               float* __restrict__ h, int K) {
    __shared__ __align__(16) unsigned char smraw[39936];
    unsigned* As2 = (unsigned*)smraw;                    // 2 x 32*20 words (5120 B)
    __half*  Bsh  = (__half*)(smraw + 5120);             // 2 x 32*264 halves (33792 B)
    float*   Cst  = (float*)smraw;                       // 32*260 floats (33280 B), epilogue only

    int bm = blockIdx.x*32;
    int tid = threadIdx.x, lane = tid & 31, warp = tid >> 5;
    int q = lane >> 2, t = lane & 3;
    int wn = warp*32;
    float acc[2][4][4];
#pragma unroll
    for (int a = 0; a < 2; a++)
#pragma unroll
        for (int b = 0; b < 4; b++)
#pragma unroll
            for (int c = 0; c < 4; c++) acc[a][b][c] = 0.f;

    int arow = tid >> 3, ac = (tid & 7)*4;      // A: 32x32, one float4/thread
    int brow = tid >> 3, bc = (tid & 7)*32;     // B: 32x256, 8 float4/thread
    const float* Ap = A + (size_t)(bm + arow)*K + ac;
    const float* Wp = W + (size_t)brow*DMODEL + bc;

    float4 ra, rb[8];
    ra = *(const float4*)(Ap);
#pragma unroll
    for (int j = 0; j < 8; j++) rb[j] = *(const float4*)(Wp + j*4);
    {
        *(uint2*)&As2[arow*20 + (tid&7)*2] = make_uint2(ph2(ra.x,ra.y), ph2(ra.z,ra.w));
#pragma unroll
        for (int j = 0; j < 8; j++)
            *(uint2*)&Bsh[brow*264 + bc + j*4] = make_uint2(ph2(rb[j].x,rb[j].y), ph2(rb[j].z,rb[j].w));
    }
    __syncthreads();

    int buf = 0;
    for (int k0 = 0; k0 < K; k0 += 32) {
        bool more = (k0 + 32) < K;
        if (more) {
            ra = *(const float4*)(Ap + k0 + 32);
#pragma unroll
            for (int j = 0; j < 8; j++) rb[j] = *(const float4*)(Wp + (size_t)(k0+32)*DMODEL + j*4);
        }
#pragma unroll
        for (int ks = 0; ks < 2; ks++) {
            unsigned af[2][4];
#pragma unroll
            for (int mt = 0; mt < 2; mt++) {
                int r = mt*16 + q;
                af[mt][0] = As2[buf*640 + r*20 + ks*8 + t];
                af[mt][1] = As2[buf*640 + (r+8)*20 + ks*8 + t];
                af[mt][2] = As2[buf*640 + r*20 + ks*8 + t + 4];
                af[mt][3] = As2[buf*640 + (r+8)*20 + ks*8 + t + 4];
            }
#pragma unroll
            for (int ntp = 0; ntp < 2; ntp++) {
                unsigned bbm[4];
                ldsm4t(bbm, &Bsh[buf*8448 + (ks*16 + (lane & 15))*264 + wn + ntp*16 + (lane >> 4)*8]);
#pragma unroll
                for (int mt = 0; mt < 2; mt++) {
                    mma_h(acc[mt][2*ntp],   af[mt], bbm[0], bbm[1]);
                    mma_h(acc[mt][2*ntp+1], af[mt], bbm[2], bbm[3]);
                }
            }
        }
        if (more) {
            int nb = buf ^ 1;
            *(uint2*)&As2[nb*640 + arow*20 + (tid&7)*2] = make_uint2(ph2(ra.x,ra.y), ph2(ra.z,ra.w));
#pragma unroll
            for (int j = 0; j < 8; j++)
                *(uint2*)&Bsh[nb*8448 + brow*264 + bc + j*4] =
                    make_uint2(ph2(rb[j].x,rb[j].y), ph2(rb[j].z,rb[j].w));
        }
        __syncthreads();
        buf ^= 1;
    }

    // stage C + bias into smem (all mainloop reads complete after last barrier)
#pragma unroll
    for (int mt = 0; mt < 2; mt++) {
        int rr = mt*16 + q;
#pragma unroll
        for (int nt = 0; nt < 4; nt++) {
            int cc = wn + nt*8 + 2*t;
            float b0 = bias[cc], b1 = bias[cc+1];
            float2 w0; w0.x = acc[mt][nt][0] + b0; w0.y = acc[mt][nt][1] + b1;
            float2 w1; w1.x = acc[mt][nt][2] + b0; w1.y = acc[mt][nt][3] + b1;
            *(float2*)&Cst[rr*260 + cc]     = w0;
            *(float2*)&Cst[(rr+8)*260 + cc] = w1;
        }
    }
    __syncthreads();

    // LN: warp w handles rows 4w .. 4w+3
#pragma unroll
    for (int i = 0; i < 4; i++) {
        int row = warp*4 + i;
        int grow = bm + row;
        float x[8];
        float* hp = h + (size_t)grow*DMODEL + lane*8;
#pragma unroll
        for (int j = 0; j < 8; j++) x[j] = Cst[row*260 + lane*8 + j] + hp[j];
        float s1 = 0.f, s2 = 0.f;
#pragma unroll
        for (int j = 0; j < 8; j++) { s1 += x[j]; s2 += x[j]*x[j]; }
#pragma unroll
        for (int off = 16; off; off >>= 1) {
            s1 += __shfl_xor_sync(0xffffffffu, s1, off);
            s2 += __shfl_xor_sync(0xffffffffu, s2, off);
        }
        float m = s1 * (1.f/DMODEL);
        float var = s2 * (1.f/DMODEL) - m*m;
        float rs = rsqrtf(var + 1e-5f);
        float4 y0, y1;
        const float* gp = g + lane*8;
        const float* bp = bb + lane*8;
        y0.x = (x[0]-m)*rs*gp[0] + bp[0]; y0.y = (x[1]-m)*rs*gp[1] + bp[1];
        y0.z = (x[2]-m)*rs*gp[2] + bp[2]; y0.w = (x[3]-m)*rs*gp[3] + bp[3];
        y1.x = (x[4]-m)*rs*gp[4] + bp[4]; y1.y = (x[5]-m)*rs*gp[5] + bp[5];
        y1.z = (x[6]-m)*rs*gp[6] + bp[6]; y1.w = (x[7]-m)*rs*gp[7] + bp[7];
        *(float4*)(hp)     = y0;
        *(float4*)(hp + 4) = y1;
    }
}

// ---------------- fp16 flash attention: fused rope, double-buffered K/V, base-2 softmax ----------------
// Dynamic smem 48KB: Q2[128*20] | K2[2][64*20] | Vh[2][64*40] | P2[128*36]
__global__ void __launch_bounds__(256) attn_h(const float* __restrict__ qkv,
                                              const float* __restrict__ cs,
                                              float* __restrict__ out) {
    extern __shared__ unsigned smd[];
    unsigned* Q2 = smd;                       // 2560 words
    unsigned* K2 = Q2 + 2560;                 // 2 x 1280 words
    __half*  Vh  = (__half*)(Q2 + 5120);      // 2 x 2560 halves
    unsigned* P2 = Q2 + 7680;                 // 4608 words

    int bh = blockIdx.y; int b = bh >> 3; int h = bh & 7;
    int qbase = blockIdx.x * 128;
    int tid = threadIdx.x, lane = tid & 31, w = tid >> 5;
    int q = lane >> 2, t = lane & 3;
    const float* base = qkv + (size_t)b*SEQ*768;
    const float scale2 = 0.25503472f;  // (1/sqrt(32)) * log2(e), folded into Q

    // ---- load Q tile 128x32 with rope + scale ----
    {
        int r = tid >> 1, c = (tid & 1)*16;
        int grow = qbase + r;
        const float* src = base + (size_t)grow*768 + h*DHEAD + c;
        float v[16];
        *(float4*)&v[0]  = *(const float4*)(src);
        *(float4*)&v[4]  = *(const float4*)(src + 4);
        *(float4*)&v[8]  = *(const float4*)(src + 8);
        *(float4*)&v[12] = *(const float4*)(src + 12);
        const float* cr = cs + (size_t)(b*SEQ + grow)*32 + (c >> 4)*16;
        float rv[16];
#pragma unroll
        for (int i = 0; i < 8; i++) {
            float co = cr[i], si = cr[8+i];
            rv[i]   = (v[i]*co - v[i+8]*si)*scale2;
            rv[i+8] = (v[i+8]*co + v[i]*si)*scale2;
        }
        *(uint4*)&Q2[r*20 + c/2] =
            make_uint4(ph2(rv[0],rv[1]), ph2(rv[2],rv[3]), ph2(rv[4],rv[5]), ph2(rv[6],rv[7]));
        *(uint4*)&Q2[r*20 + c/2 + 4] =
            make_uint4(ph2(rv[8],rv[9]), ph2(rv[10],rv[11]), ph2(rv[12],rv[13]), ph2(rv[14],rv[15]));
    }
    __syncthreads();

    unsigned qf[2][4];
#pragma unroll
    for (int ks = 0; ks < 2; ks++) {
        int r = w*16 + q;
        qf[ks][0] = Q2[r*20 + ks*8 + t];
        qf[ks][1] = Q2[(r+8)*20 + ks*8 + t];
        qf[ks][2] = Q2[r*20 + ks*8 + t + 4];
        qf[ks][3] = Q2[(r+8)*20 + ks*8 + t + 4];
    }

    float accO[4][4] = {};
    float m0 = -1e30f, m1 = -1e30f, l0 = 0.f, l1 = 0.f;

    // K/V loader: warps 0-3 K (with rope), warps 4-7 V
    int isV = tid >> 7;
    int t2 = tid & 127;
    int kr = t2 >> 1, c = (t2 & 1)*16;
    const float* kvsrc = base + (size_t)kr*768 + (isV ? 2*DMODEL : DMODEL) + h*DHEAD + c;
    const float* csrc  = cs + (size_t)(b*SEQ + kr)*32 + (c >> 4)*16;

    float pv[16], pc[16];
    *(float4*)&pv[0]  = *(const float4*)(kvsrc);
    *(float4*)&pv[4]  = *(const float4*)(kvsrc + 4);
    *(float4*)&pv[8]  = *(const float4*)(kvsrc + 8);
    *(float4*)&pv[12] = *(const float4*)(kvsrc + 12);
    if (!isV) {
        *(float4*)&pc[0]  = *(const float4*)(csrc);
        *(float4*)&pc[4]  = *(const float4*)(csrc + 4);
        *(float4*)&pc[8]  = *(const float4*)(csrc + 8);
        *(float4*)&pc[12] = *(const float4*)(csrc + 12);
    }
    // commit chunk 0 -> buffer 0
    if (!isV) {
        float rv[16];
#pragma unroll
        for (int i = 0; i < 8; i++) {
            float co = pc[i], si = pc[8+i];
            rv[i]   = pv[i]*co - pv[i+8]*si;
            rv[i+8] = pv[i+8]*co + pv[i]*si;
        }
        *(uint4*)&K2[kr*20 + c/2] =
            make_uint4(ph2(rv[0],rv[1]), ph2(rv[2],rv[3]), ph2(rv[4],rv[5]), ph2(rv[6],rv[7]));
        *(uint4*)&K2[kr*20 + c/2 + 4] =
            make_uint4(ph2(rv[8],rv[9]), ph2(rv[10],rv[11]), ph2(rv[12],rv[13]), ph2(rv[14],rv[15]));
    } else {
        *(uint4*)&Vh[kr*40 + c] =
            make_uint4(ph2(pv[0],pv[1]), ph2(pv[2],pv[3]), ph2(pv[4],pv[5]), ph2(pv[6],pv[7]));
        *(uint4*)&Vh[kr*40 + c + 8] =
            make_uint4(ph2(pv[8],pv[9]), ph2(pv[10],pv[11]), ph2(pv[12],pv[13]), ph2(pv[14],pv[15]));
    }
    __syncthreads();

    int buf = 0;
    for (int kc0 = 0; kc0 < SEQ; kc0 += 64) {
        bool more = (kc0 + 64) < SEQ;
        // prefetch next chunk into registers (overlaps with compute)
        if (more) {
            const float* ns = kvsrc + (size_t)(kc0 + 64)*768;
            *(float4*)&pv[0]  = *(const float4*)(ns);
            *(float4*)&pv[4]  = *(const float4*)(ns + 4);
            *(float4*)&pv[8]  = *(const float4*)(ns + 8);
            *(float4*)&pv[12] = *(const float4*)(ns + 12);
            if (!isV) {
                const float* nc = csrc + (size_t)(kc0 + 64)*32;
                *(float4*)&pc[0]  = *(const float4*)(nc);
                *(float4*)&pc[4]  = *(const float4*)(nc + 4);
                *(float4*)&pc[8]  = *(const float4*)(nc + 8);
                *(float4*)&pc[12] = *(const float4*)(nc + 12);
            }
        }
        const unsigned* Kb = K2 + buf*1280;
        const __half*  Vb = Vh + buf*2560;

        // S = Q @ K^T
        float s[8][4] = {};
#pragma unroll
        for (int ks = 0; ks < 2; ks++) {
#pragma unroll
            for (int nt = 0; nt < 8; nt++) {
                int key = nt*8 + q;
                unsigned b0 = Kb[key*20 + ks*8 + t];
                unsigned b1 = Kb[key*20 + ks*8 + t + 4];
                mma_h(s[nt], qf[ks], b0, b1);
            }
        }

        // online softmax (base 2)
        float rm0 = -1e30f, rm1 = -1e30f;
#pragma unroll
        for (int nt = 0; nt < 8; nt++) {
            rm0 = fmaxf(rm0, fmaxf(s[nt][0], s[nt][1]));
            rm1 = fmaxf(rm1, fmaxf(s[nt][2], s[nt][3]));
        }
        rm0 = fmaxf(rm0, __shfl_xor_sync(0xffffffffu, rm0, 1));
        rm0 = fmaxf(rm0, __shfl_xor_sync(0xffffffffu, rm0, 2));
        rm1 = fmaxf(rm1, __shfl_xor_sync(0xffffffffu, rm1, 1));
        rm1 = fmaxf(rm1, __shfl_xor_sync(0xffffffffu, rm1, 2));
        float mn0 = fmaxf(m0, rm0), mn1 = fmaxf(m1, rm1);
        float cf0 = ex2(m0 - mn0), cf1 = ex2(m1 - mn1);
        m0 = mn0; m1 = mn1;
        float rs0 = 0.f, rs1 = 0.f;
#pragma unroll
        for (int nt = 0; nt < 8; nt++) {
            s[nt][0] = ex2(s[nt][0] - mn0);
            s[nt][1] = ex2(s[nt][1] - mn0);
            s[nt][2] = ex2(s[nt][2] - mn1);
            s[nt][3] = ex2(s[nt][3] - mn1);
            rs0 += s[nt][0] + s[nt][1];
            rs1 += s[nt][2] + s[nt][3];
        }
        rs0 += __shfl_xor_sync(0xffffffffu, rs0, 1);
        rs0 += __shfl_xor_sync(0xffffffffu, rs0, 2);
        rs1 += __shfl_xor_sync(0xffffffffu, rs1, 1);
        rs1 += __shfl_xor_sync(0xffffffffu, rs1, 2);
        l0 = l0*cf0 + rs0; l1 = l1*cf1 + rs1;
#pragma unroll
        for (int nt = 0; nt < 4; nt++) {
            accO[nt][0] *= cf0; accO[nt][1] *= cf0;
            accO[nt][2] *= cf1; accO[nt][3] *= cf1;
        }

        // P -> smem (warp-private rows)
        {
            int r = w*16 + q;
#pragma unroll
            for (int nt = 0; nt < 8; nt++) {
                P2[r*36 + nt*4 + t]     = ph2(s[nt][0], s[nt][1]);
                P2[(r+8)*36 + nt*4 + t] = ph2(s[nt][2], s[nt][3]);
            }
        }
        __syncwarp();

        // O += P @ V
#pragma unroll
        for (int ks = 0; ks < 4; ks++) {
            unsigned pa[4];
            int r = w*16 + q;
            pa[0] = P2[r*36 + ks*8 + t];
            pa[1] = P2[(r+8)*36 + ks*8 + t];
            pa[2] = P2[r*36 + ks*8 + t + 4];
            pa[3] = P2[(r+8)*36 + ks*8 + t + 4];
#pragma unroll
            for (int ntp = 0; ntp < 2; ntp++) {
                unsigned bbv[4];
                ldsm4t(bbv, &Vb[(ks*16 + (lane & 15))*40 + ntp*16 + (lane >> 4)*8]);
                mma_h(accO[2*ntp],   pa, bbv[0], bbv[1]);
                mma_h(accO[2*ntp+1], pa, bbv[2], bbv[3]);
            }
        }

        // commit prefetched chunk to the other buffer (consumed next iter)
        if (more) {
            int nb = buf ^ 1;
            if (!isV) {
                float rv[16];
#pragma unroll
                for (int i = 0; i < 8; i++) {
                    float co = pc[i], si = pc[8+i];
                    rv[i]   = pv[i]*co - pv[i+8]*si;
                    rv[i+8] = pv[i+8]*co + pv[i]*si;
                }
                *(uint4*)&K2[nb*1280 + kr*20 + c/2] =
                    make_uint4(ph2(rv[0],rv[1]), ph2(rv[2],rv[3]), ph2(rv[4],rv[5]), ph2(rv[6],rv[7]));
                *(uint4*)&K2[nb*1280 + kr*20 + c/2 + 4] =
                    make_uint4(ph2(rv[8],rv[9]), ph2(rv[10],rv[11]), ph2(rv[12],rv[13]), ph2(rv[14],rv[15]));
            } else {
                *(uint4*)&Vh[nb*2560 + kr*40 + c] =
                    make_uint4(ph2(pv[0],pv[1]), ph2(pv[2],pv[3]), ph2(pv[4],pv[5]), ph2(pv[6],pv[7]));
                *(uint4*)&Vh[nb*2560 + kr*40 + c + 8] =
                    make_uint4(ph2(pv[8],pv[9]), ph2(pv[10],pv[11]), ph2(pv[12],pv[13]), ph2(pv[14],pv[15]));
            }
        }
        __syncthreads();
        buf ^= 1;
    }

    // epilogue
    float il0 = 1.f/l0, il1 = 1.f/l1;
    int qr = qbase + w*16 + q;
#pragma unroll
    for (int nt = 0; nt < 4; nt++) {
        int cc = h*DHEAD + nt*8 + 2*t;
        float2 v0; v0.x = accO[nt][0]*il0; v0.y = accO[nt][1]*il0;
        float2 v1; v1.x = accO[nt][2]*il1; v1.y = accO[nt][3]*il1;
        *(float2*)&out[(size_t)(b*SEQ + qr)*DMODEL + cc]     = v0;
        *(float2*)&out[(size_t)(b*SEQ + qr + 8)*DMODEL + cc] = v1;
    }
}

// ---------------- host ----------------
extern "C" void kernel_launch(void* const* d_in, const int* in_sizes, int n_in,
                              void* d_out, int out_size) {
    const float* h_in    = (const float*)d_in[0];
    const float* pos     = (const float*)d_in[1];
    const float* proj_w  = (const float*)d_in[2];
    const float* proj_b  = (const float*)d_in[3];
    const float* qkv_w   = (const float*)d_in[4];
    const float* out_w   = (const float*)d_in[5];
    const float* out_b   = (const float*)d_in[6];
    const float* O_w     = (const float*)d_in[7];
    const float* O_b     = (const float*)d_in[8];
    const float* ffn1_w  = (const float*)d_in[9];
    const float* ffn1_b  = (const float*)d_in[10];
    const float* ffn2_w  = (const float*)d_in[11];
    const float* ffn2_b  = (const float*)d_in[12];
    const float* ln1_g   = (const float*)d_in[13];
    const float* ln1_b   = (const float*)d_in[14];
    const float* ln2_g   = (const float*)d_in[15];
    const float* ln2_b   = (const float*)d_in[16];
    const float* final_w = (const float*)d_in[17];
    float* out = (float*)d_out;

    float *ph, *pqkv, *pattn, *pffn, *pcs, *pWf, *pbf;
    cudaGetSymbolAddress((void**)&ph,   g_h);
    cudaGetSymbolAddress((void**)&pqkv, g_qkv);
    cudaGetSymbolAddress((void**)&pattn,g_attn);
    cudaGetSymbolAddress((void**)&pffn, g_ffn);
    cudaGetSymbolAddress((void**)&pcs,  g_cs);
    cudaGetSymbolAddress((void**)&pWf,  g_Wf);
    cudaGetSymbolAddress((void**)&pbf,  g_bf);

    cudaFuncSetAttribute(attn_h, cudaFuncAttributeMaxDynamicSharedMemorySize, 49152);

    freqs_kernel<<<ROWS*16/256, 256>>>(pos, pcs);
    gemm_h<2,0,0><<<dim3(2,4,4), 256>>>(out_w, O_w, nullptr, pWf,
                                        DMODEL, DMODEL, DMODEL,
                                        DMODEL*DMODEL, DMODEL*DMODEL, DMODEL*DMODEL);
    fuse_bias_kernel<<<NLAYER, 256>>>(out_b, O_w, O_b, pbf);
    proj_kernel<<<ROWS*64/256, 256>>>(h_in, proj_w, proj_b, ph);

    for (int l = 0; l < NLAYER; l++) {
        gemm_h<4,0,0><<<dim3(6,64), 256>>>(ph, qkv_w + (size_t)l*DMODEL*3*DMODEL,
                                           nullptr, pqkv, ROWS, DMODEL, 3*DMODEL, 0, 0, 0);
        attn_h<<<dim3(SEQ/128, BATCH*NHEAD), 256, 49152>>>(pqkv, pcs, pattn);
        gemm_ln<<<ROWS/32, 256>>>(pattn, pWf + (size_t)l*DMODEL*DMODEL, pbf + l*DMODEL,
                                  ln1_g + l*DMODEL, ln1_b + l*DMODEL, ph, DMODEL);
        gemm_h<4,1,1><<<dim3(4,64), 256>>>(ph, ffn1_w + (size_t)l*DMODEL*2*DMODEL,
                                           ffn1_b + l*2*DMODEL, pffn, ROWS, DMODEL, 2*DMODEL, 0, 0, 0);
        gemm_ln<<<ROWS/32, 256>>>(pffn, ffn2_w + (size_t)l*2*DMODEL*DMODEL, ffn2_b + l*DMODEL,
                                  ln2_g + l*DMODEL, ln2_b + l*DMODEL, ph, 2*DMODEL);
    }
    gemm_h<2,0,0><<<dim3(2,128), 256>>>(ph, final_w, nullptr, out, ROWS, DMODEL, DMODEL, 0, 0, 0);
}

// round 8
// speedup vs baseline: 1.2128x; 1.2128x over previous
#include <cuda_runtime.h>
#include <cuda_fp16.h>
#include <math.h>

#define BATCH 4
#define SEQ 2048
#define DMODEL 256
#define NHEAD 8
#define DHEAD 32
#define NLAYER 4
#define ROWS (BATCH*SEQ)   // 8192

// ---------------- scratch ----------------
__device__ float g_h   [ROWS*DMODEL];
__device__ float g_qkv [ROWS*3*DMODEL];
__device__ float g_attn[ROWS*DMODEL];
__device__ float g_ffn [ROWS*2*DMODEL];
__device__ float g_cs  [ROWS*32];
__device__ float g_Wf  [NLAYER*DMODEL*DMODEL];
__device__ float g_bf  [NLAYER*DMODEL];

// ---------------- helpers ----------------
__device__ __forceinline__ unsigned ph2(float a, float b) {
    __half2 h = __floats2half2_rn(a, b);
    return *reinterpret_cast<unsigned*>(&h);
}

__device__ __forceinline__ float ex2(float x) {
    float y; asm("ex2.approx.ftz.f32 %0, %1;" : "=f"(y) : "f"(x)); return y;
}

__device__ __forceinline__ void mma_h(float* d, const unsigned* a, unsigned b0, unsigned b1) {
    asm("mma.sync.aligned.m16n8k16.row.col.f32.f16.f16.f32 "
        "{%0,%1,%2,%3},{%4,%5,%6,%7},{%8,%9},{%0,%1,%2,%3};"
        : "+f"(d[0]), "+f"(d[1]), "+f"(d[2]), "+f"(d[3])
        : "r"(a[0]), "r"(a[1]), "r"(a[2]), "r"(a[3]), "r"(b0), "r"(b1));
}

__device__ __forceinline__ void ldsm4t(unsigned* r, const void* p) {
    unsigned a = (unsigned)__cvta_generic_to_shared(p);
    asm volatile("ldmatrix.sync.aligned.m8n8.x4.trans.shared.b16 {%0,%1,%2,%3}, [%4];"
        : "=r"(r[0]), "=r"(r[1]), "=r"(r[2]), "=r"(r[3]) : "r"(a));
}

// ---------------- small setup kernels ----------------
__global__ void proj_kernel(const float* __restrict__ hin, const float* __restrict__ pw,
                            const float* __restrict__ pb, float* __restrict__ hout) {
    int idx = blockIdx.x*256 + threadIdx.x;       // ROWS*64
    int row = idx >> 6, c4 = idx & 63;
    float4 w = ((const float4*)pw)[c4];
    float4 b = ((const float4*)pb)[c4];
    float hv = hin[row];
    float4 r; r.x = hv*w.x + b.x; r.y = hv*w.y + b.y; r.z = hv*w.z + b.z; r.w = hv*w.w + b.w;
    ((float4*)hout)[row*64 + c4] = r;
}

__global__ void freqs_kernel(const float* __restrict__ pos, float* __restrict__ cs) {
    int idx = blockIdx.x*blockDim.x + threadIdx.x;   // ROWS*16
    int row = idx >> 4; int r = idx & 15; int axis = r >> 3; int fi = r & 7;
    float coord = pos[row*2 + axis];
    float inv = powf(10000.f, -(float)fi * 0.125f);
    float ang = coord * 64.f * inv;
    float s, c; sincosf(ang, &s, &c);
    cs[row*32 + axis*16 + fi]     = c;
    cs[row*32 + axis*16 + 8 + fi] = s;
}

__global__ void fuse_bias_kernel(const float* __restrict__ out_b, const float* __restrict__ O_w,
                                 const float* __restrict__ O_b, float* __restrict__ bf) {
    int l = blockIdx.x, j = threadIdx.x;
    const float* wb = O_w + (size_t)l*DMODEL*DMODEL;
    const float* ob = out_b + l*DMODEL;
    float acc = O_b[l*DMODEL + j];
    for (int i = 0; i < DMODEL; i++) acc = fmaf(ob[i], wb[i*DMODEL + j], acc);
    bf[l*DMODEL + j] = acc;
}

// ---------------- fp16 GEMM: C[M,N] = A[M,K] @ W[K,N] (+bias)(+relu), batched via z ----------------
// BM = MT*32, BN=128, BK=32. 8 warps (2M x 4N).
template<int MT, int HASB, int RELU>
__global__ void __launch_bounds__(256) gemm_h(const float* __restrict__ A, const float* __restrict__ W,
                                              const float* __restrict__ bias, float* __restrict__ C,
                                              int M, int K, int N, int sA, int sW, int sC) {
    __shared__ unsigned As2[2][MT*32*20];
    __shared__ __half  Bsh[2][32*136];
    A += (size_t)blockIdx.z*sA; W += (size_t)blockIdx.z*sW; C += (size_t)blockIdx.z*sC;
    const int BM = MT*32;
    int bm = blockIdx.y*BM, bn = blockIdx.x*128;
    int tid = threadIdx.x, lane = tid & 31, warp = tid >> 5;
    int q = lane >> 2, t = lane & 3;
    int wm = (warp >> 2)*(16*MT), wn = (warp & 3)*32;
    float acc[MT][4][4];
#pragma unroll
    for (int a = 0; a < MT; a++)
#pragma unroll
        for (int b = 0; b < 4; b++)
#pragma unroll
            for (int c = 0; c < 4; c++) acc[a][b][c] = 0.f;

    int arow, acolf;
    if (MT == 4) { arow = tid >> 1; acolf = (tid & 1)*16; }
    else         { arow = tid >> 2; acolf = (tid & 3)*8; }
    int brow = tid >> 4, bcol = (tid & 15)*8;
    const float* Ap = A + (size_t)(bm + arow)*K + acolf;
    const float* Wp = W + (size_t)brow*N + bn + bcol;

    float4 ra[4], rb[4];
    ra[0] = *(const float4*)(Ap);
    ra[1] = *(const float4*)(Ap + 4);
    if (MT == 4) { ra[2] = *(const float4*)(Ap + 8); ra[3] = *(const float4*)(Ap + 12); }
    rb[0] = *(const float4*)(Wp);
    rb[1] = *(const float4*)(Wp + 4);
    rb[2] = *(const float4*)(Wp + (size_t)16*N);
    rb[3] = *(const float4*)(Wp + (size_t)16*N + 4);
    {
        *(uint4*)&As2[0][arow*20 + acolf/2] =
            make_uint4(ph2(ra[0].x,ra[0].y), ph2(ra[0].z,ra[0].w), ph2(ra[1].x,ra[1].y), ph2(ra[1].z,ra[1].w));
        if (MT == 4)
            *(uint4*)&As2[0][arow*20 + acolf/2 + 4] =
                make_uint4(ph2(ra[2].x,ra[2].y), ph2(ra[2].z,ra[2].w), ph2(ra[3].x,ra[3].y), ph2(ra[3].z,ra[3].w));
        *(uint4*)&Bsh[0][brow*136 + bcol] =
            make_uint4(ph2(rb[0].x,rb[0].y), ph2(rb[0].z,rb[0].w), ph2(rb[1].x,rb[1].y), ph2(rb[1].z,rb[1].w));
        *(uint4*)&Bsh[0][(brow+16)*136 + bcol] =
            make_uint4(ph2(rb[2].x,rb[2].y), ph2(rb[2].z,rb[2].w), ph2(rb[3].x,rb[3].y), ph2(rb[3].z,rb[3].w));
    }
    __syncthreads();

    int buf = 0;
    for (int k0 = 0; k0 < K; k0 += 32) {
        bool more = (k0 + 32) < K;
        if (more) {
            ra[0] = *(const float4*)(Ap + k0 + 32);
            ra[1] = *(const float4*)(Ap + k0 + 36);
            if (MT == 4) { ra[2] = *(const float4*)(Ap + k0 + 40); ra[3] = *(const float4*)(Ap + k0 + 44); }
            rb[0] = *(const float4*)(Wp + (size_t)(k0+32)*N);
            rb[1] = *(const float4*)(Wp + (size_t)(k0+32)*N + 4);
            rb[2] = *(const float4*)(Wp + (size_t)(k0+48)*N);
            rb[3] = *(const float4*)(Wp + (size_t)(k0+48)*N + 4);
        }
#pragma unroll
        for (int ks = 0; ks < 2; ks++) {
            unsigned af[MT][4];
#pragma unroll
            for (int mt = 0; mt < MT; mt++) {
                int r = wm + mt*16 + q;
                af[mt][0] = As2[buf][r*20 + ks*8 + t];
                af[mt][1] = As2[buf][(r+8)*20 + ks*8 + t];
                af[mt][2] = As2[buf][r*20 + ks*8 + t + 4];
                af[mt][3] = As2[buf][(r+8)*20 + ks*8 + t + 4];
            }
#pragma unroll
            for (int ntp = 0; ntp < 2; ntp++) {
                unsigned bb[4];
                ldsm4t(bb, &Bsh[buf][(ks*16 + (lane & 15))*136 + wn + ntp*16 + (lane >> 4)*8]);
#pragma unroll
                for (int mt = 0; mt < MT; mt++) {
                    mma_h(acc[mt][2*ntp],   af[mt], bb[0], bb[1]);
                    mma_h(acc[mt][2*ntp+1], af[mt], bb[2], bb[3]);
                }
            }
        }
        if (more) {
            int nb = buf ^ 1;
            *(uint4*)&As2[nb][arow*20 + acolf/2] =
                make_uint4(ph2(ra[0].x,ra[0].y), ph2(ra[0].z,ra[0].w), ph2(ra[1].x,ra[1].y), ph2(ra[1].z,ra[1].w));
            if (MT == 4)
                *(uint4*)&As2[nb][arow*20 + acolf/2 + 4] =
                    make_uint4(ph2(ra[2].x,ra[2].y), ph2(ra[2].z,ra[2].w), ph2(ra[3].x,ra[3].y), ph2(ra[3].z,ra[3].w));
            *(uint4*)&Bsh[nb][brow*136 + bcol] =
                make_uint4(ph2(rb[0].x,rb[0].y), ph2(rb[0].z,rb[0].w), ph2(rb[1].x,rb[1].y), ph2(rb[1].z,rb[1].w));
            *(uint4*)&Bsh[nb][(brow+16)*136 + bcol] =
                make_uint4(ph2(rb[2].x,rb[2].y), ph2(rb[2].z,rb[2].w), ph2(rb[3].x,rb[3].y), ph2(rb[3].z,rb[3].w));
        }
        __syncthreads();
        buf ^= 1;
    }

#pragma unroll
    for (int mt = 0; mt < MT; mt++) {
        int r0 = bm + wm + mt*16 + q;
#pragma unroll
        for (int nt = 0; nt < 4; nt++) {
            int c0 = bn + wn + nt*8 + 2*t;
            float b0 = 0.f, b1 = 0.f;
            if (HASB) { b0 = bias[c0]; b1 = bias[c0+1]; }
            float v0 = acc[mt][nt][0] + b0, v1 = acc[mt][nt][1] + b1;
            float v2 = acc[mt][nt][2] + b0, v3 = acc[mt][nt][3] + b1;
            if (RELU) { v0=fmaxf(v0,0.f); v1=fmaxf(v1,0.f); v2=fmaxf(v2,0.f); v3=fmaxf(v3,0.f); }
            float2 w0; w0.x = v0; w0.y = v1;
            float2 w1; w1.x = v2; w1.y = v3;
            *(float2*)&C[(size_t)r0*N + c0]     = w0;
            *(float2*)&C[(size_t)(r0+8)*N + c0] = w1;
        }
    }
}

// ---------------- fp16 flash attention (round-6 structure) + fused rope + base-2 softmax ----------------
// Block = (b,h,128 q rows), 8 warps, 64-key chunks, single-buffered K/V with register prefetch.
__global__ void __launch_bounds__(256) attn_h(const float* __restrict__ qkv,
                                              const float* __restrict__ cs,
                                              float* __restrict__ out) {
    __shared__ unsigned Q2[128*20];
    __shared__ unsigned K2[64*20];
    __shared__ __half  Vh[64*40];
    __shared__ unsigned P2[128*36];

    int bh = blockIdx.y; int b = bh >> 3; int h = bh & 7;
    int qbase = blockIdx.x * 128;
    int tid = threadIdx.x, lane = tid & 31, w = tid >> 5;
    int q = lane >> 2, t = lane & 3;
    const float* base = qkv + (size_t)b*SEQ*768;
    const float scale2 = 0.25503472f;  // (1/sqrt(32)) * log2(e), folded into Q

    // ---- load Q tile 128x32 with rope + scale ----
    {
        int r = tid >> 1, c = (tid & 1)*16;
        int grow = qbase + r;
        const float* src = base + (size_t)grow*768 + h*DHEAD + c;
        float v[16];
        *(float4*)&v[0]  = *(const float4*)(src);
        *(float4*)&v[4]  = *(const float4*)(src + 4);
        *(float4*)&v[8]  = *(const float4*)(src + 8);
        *(float4*)&v[12] = *(const float4*)(src + 12);
        const float* cr = cs + (size_t)(b*SEQ + grow)*32 + (c >> 4)*16;
        float rv[16];
#pragma unroll
        for (int i = 0; i < 8; i++) {
            float co = cr[i], si = cr[8+i];
            rv[i]   = (v[i]*co - v[i+8]*si)*scale2;
            rv[i+8] = (v[i+8]*co + v[i]*si)*scale2;
        }
        *(uint4*)&Q2[r*20 + c/2] =
            make_uint4(ph2(rv[0],rv[1]), ph2(rv[2],rv[3]), ph2(rv[4],rv[5]), ph2(rv[6],rv[7]));
        *(uint4*)&Q2[r*20 + c/2 + 4] =
            make_uint4(ph2(rv[8],rv[9]), ph2(rv[10],rv[11]), ph2(rv[12],rv[13]), ph2(rv[14],rv[15]));
    }
    __syncthreads();

    unsigned qf[2][4];
#pragma unroll
    for (int ks = 0; ks < 2; ks++) {
        int r = w*16 + q;
        qf[ks][0] = Q2[r*20 + ks*8 + t];
        qf[ks][1] = Q2[(r+8)*20 + ks*8 + t];
        qf[ks][2] = Q2[r*20 + ks*8 + t + 4];
        qf[ks][3] = Q2[(r+8)*20 + ks*8 + t + 4];
    }

    float accO[4][4] = {};
    float m0 = -1e30f, m1 = -1e30f, l0 = 0.f, l1 = 0.f;

    // K/V loader: warps 0-3 load K (with rope), warps 4-7 load V
    int isV = tid >> 7;
    int t2 = tid & 127;
    int kr = t2 >> 1, c = (t2 & 1)*16;
    const float* kvsrc = base + (size_t)kr*768 + (isV ? 2*DMODEL : DMODEL) + h*DHEAD + c;
    const float* csrc  = cs + (size_t)(b*SEQ + kr)*32 + (c >> 4)*16;

    float pv[16], pc[16];
    *(float4*)&pv[0]  = *(const float4*)(kvsrc);
    *(float4*)&pv[4]  = *(const float4*)(kvsrc + 4);
    *(float4*)&pv[8]  = *(const float4*)(kvsrc + 8);
    *(float4*)&pv[12] = *(const float4*)(kvsrc + 12);
    if (!isV) {
        *(float4*)&pc[0]  = *(const float4*)(csrc);
        *(float4*)&pc[4]  = *(const float4*)(csrc + 4);
        *(float4*)&pc[8]  = *(const float4*)(csrc + 8);
        *(float4*)&pc[12] = *(const float4*)(csrc + 12);
    }

    for (int kc0 = 0; kc0 < SEQ; kc0 += 64) {
        // commit prefetched chunk
        if (!isV) {
            float rv[16];
#pragma unroll
            for (int i = 0; i < 8; i++) {
                float co = pc[i], si = pc[8+i];
                rv[i]   = pv[i]*co - pv[i+8]*si;
                rv[i+8] = pv[i+8]*co + pv[i]*si;
            }
            *(uint4*)&K2[kr*20 + c/2] =
                make_uint4(ph2(rv[0],rv[1]), ph2(rv[2],rv[3]), ph2(rv[4],rv[5]), ph2(rv[6],rv[7]));
            *(uint4*)&K2[kr*20 + c/2 + 4] =
                make_uint4(ph2(rv[8],rv[9]), ph2(rv[10],rv[11]), ph2(rv[12],rv[13]), ph2(rv[14],rv[15]));
        } else {
            *(uint4*)&Vh[kr*40 + c] =
                make_uint4(ph2(pv[0],pv[1]), ph2(pv[2],pv[3]), ph2(pv[4],pv[5]), ph2(pv[6],pv[7]));
            *(uint4*)&Vh[kr*40 + c + 8] =
                make_uint4(ph2(pv[8],pv[9]), ph2(pv[10],pv[11]), ph2(pv[12],pv[13]), ph2(pv[14],pv[15]));
        }
        __syncthreads();

        // prefetch next chunk
        if (kc0 + 64 < SEQ) {
            const float* ns = kvsrc + (size_t)(kc0 + 64)*768;
            *(float4*)&pv[0]  = *(const float4*)(ns);
            *(float4*)&pv[4]  = *(const float4*)(ns + 4);
            *(float4*)&pv[8]  = *(const float4*)(ns + 8);
            *(float4*)&pv[12] = *(const float4*)(ns + 12);
            if (!isV) {
                const float* nc = csrc + (size_t)(kc0 + 64)*32;
                *(float4*)&pc[0]  = *(const float4*)(nc);
                *(float4*)&pc[4]  = *(const float4*)(nc + 4);
                *(float4*)&pc[8]  = *(const float4*)(nc + 8);
                *(float4*)&pc[12] = *(const float4*)(nc + 12);
            }
        }

        // S = Q @ K^T : m16 x n64 x k32
        float s[8][4] = {};
#pragma unroll
        for (int ks = 0; ks < 2; ks++) {
#pragma unroll
            for (int nt = 0; nt < 8; nt++) {
                int key = nt*8 + q;
                unsigned b0 = K2[key*20 + ks*8 + t];
                unsigned b1 = K2[key*20 + ks*8 + t + 4];
                mma_h(s[nt], qf[ks], b0, b1);
            }
        }

        // online softmax (base 2)
        float rm0 = -1e30f, rm1 = -1e30f;
#pragma unroll
        for (int nt = 0; nt < 8; nt++) {
            rm0 = fmaxf(rm0, fmaxf(s[nt][0], s[nt][1]));
            rm1 = fmaxf(rm1, fmaxf(s[nt][2], s[nt][3]));
        }
        rm0 = fmaxf(rm0, __shfl_xor_sync(0xffffffffu, rm0, 1));
        rm0 = fmaxf(rm0, __shfl_xor_sync(0xffffffffu, rm0, 2));
        rm1 = fmaxf(rm1, __shfl_xor_sync(0xffffffffu, rm1, 1));
        rm1 = fmaxf(rm1, __shfl_xor_sync(0xffffffffu, rm1, 2));
        float mn0 = fmaxf(m0, rm0), mn1 = fmaxf(m1, rm1);
        float cf0 = ex2(m0 - mn0), cf1 = ex2(m1 - mn1);
        m0 = mn0; m1 = mn1;
        float rs0 = 0.f, rs1 = 0.f;
#pragma unroll
        for (int nt = 0; nt < 8; nt++) {
            s[nt][0] = ex2(s[nt][0] - mn0);
            s[nt][1] = ex2(s[nt][1] - mn0);
            s[nt][2] = ex2(s[nt][2] - mn1);
            s[nt][3] = ex2(s[nt][3] - mn1);
            rs0 += s[nt][0] + s[nt][1];
            rs1 += s[nt][2] + s[nt][3];
        }
        rs0 += __shfl_xor_sync(0xffffffffu, rs0, 1);
        rs0 += __shfl_xor_sync(0xffffffffu, rs0, 2);
        rs1 += __shfl_xor_sync(0xffffffffu, rs1, 1);
        rs1 += __shfl_xor_sync(0xffffffffu, rs1, 2);
        l0 = l0*cf0 + rs0; l1 = l1*cf1 + rs1;
#pragma unroll
        for (int nt = 0; nt < 4; nt++) {
            accO[nt][0] *= cf0; accO[nt][1] *= cf0;
            accO[nt][2] *= cf1; accO[nt][3] *= cf1;
        }

        // P -> smem (warp-private rows)
        {
            int r = w*16 + q;
#pragma unroll
            for (int nt = 0; nt < 8; nt++) {
                P2[r*36 + nt*4 + t]     = ph2(s[nt][0], s[nt][1]);
                P2[(r+8)*36 + nt*4 + t] = ph2(s[nt][2], s[nt][3]);
            }
        }
        __syncwarp();

        // O += P @ V
#pragma unroll
        for (int ks = 0; ks < 4; ks++) {
            unsigned pa[4];
            int r = w*16 + q;
            pa[0] = P2[r*36 + ks*8 + t];
            pa[1] = P2[(r+8)*36 + ks*8 + t];
            pa[2] = P2[r*36 + ks*8 + t + 4];
            pa[3] = P2[(r+8)*36 + ks*8 + t + 4];
#pragma unroll
            for (int ntp = 0; ntp < 2; ntp++) {
                unsigned bbv[4];
                ldsm4t(bbv, &Vh[(ks*16 + (lane & 15))*40 + ntp*16 + (lane >> 4)*8]);
                mma_h(accO[2*ntp],   pa, bbv[0], bbv[1]);
                mma_h(accO[2*ntp+1], pa, bbv[2], bbv[3]);
            }
        }
        __syncthreads();
    }

    // epilogue
    float il0 = 1.f/l0, il1 = 1.f/l1;
    int qr = qbase + w*16 + q;
#pragma unroll
    for (int nt = 0; nt < 4; nt++) {
        int cc = h*DHEAD + nt*8 + 2*t;
        float2 v0; v0.x = accO[nt][0]*il0; v0.y = accO[nt][1]*il0;
        float2 v1; v1.x = accO[nt][2]*il1; v1.y = accO[nt][3]*il1;
        *(float2*)&out[(size_t)(b*SEQ + qr)*DMODEL + cc]     = v0;
        *(float2*)&out[(size_t)(b*SEQ + qr + 8)*DMODEL + cc] = v1;
    }
}

// ---------------- residual add + layernorm: 4 rows/block, float4/thread ----------------
__global__ void add_ln4(float* __restrict__ h, const float* __restrict__ o,
                        const float* __restrict__ g, const float* __restrict__ bb) {
    __shared__ float red[16];
    int tid = threadIdx.x;
    int row = blockIdx.x*4 + (tid >> 6);
    int c4 = tid & 63;
    int lane = tid & 31, warp = tid >> 5;
    float4 hv = ((const float4*)h)[row*64 + c4];
    float4 ov = ((const float4*)o)[row*64 + c4];
    float x0 = hv.x + ov.x, x1 = hv.y + ov.y, x2 = hv.z + ov.z, x3 = hv.w + ov.w;
    float s1 = x0 + x1 + x2 + x3;
    float s2 = x0*x0 + x1*x1 + x2*x2 + x3*x3;
#pragma unroll
    for (int off = 16; off; off >>= 1) {
        s1 += __shfl_xor_sync(0xffffffffu, s1, off);
        s2 += __shfl_xor_sync(0xffffffffu, s2, off);
    }
    if (lane == 0) { red[warp] = s1; red[8 + warp] = s2; }
    __syncthreads();
    int wp = warp & ~1;  // partner pair base for this row
    float t1 = red[wp] + red[wp+1];
    float t2 = red[8+wp] + red[8+wp+1];
    float m = t1 * (1.f/DMODEL);
    float var = t2 * (1.f/DMODEL) - m*m;
    float rs = rsqrtf(var + 1e-5f);
    float4 gv = ((const float4*)g)[c4];
    float4 bv = ((const float4*)bb)[c4];
    float4 y;
    y.x = (x0 - m)*rs*gv.x + bv.x;
    y.y = (x1 - m)*rs*gv.y + bv.y;
    y.z = (x2 - m)*rs*gv.z + bv.z;
    y.w = (x3 - m)*rs*gv.w + bv.w;
    ((float4*)h)[row*64 + c4] = y;
}

// ---------------- host ----------------
extern "C" void kernel_launch(void* const* d_in, const int* in_sizes, int n_in,
                              void* d_out, int out_size) {
    const float* h_in    = (const float*)d_in[0];
    const float* pos     = (const float*)d_in[1];
    const float* proj_w  = (const float*)d_in[2];
    const float* proj_b  = (const float*)d_in[3];
    const float* qkv_w   = (const float*)d_in[4];
    const float* out_w   = (const float*)d_in[5];
    const float* out_b   = (const float*)d_in[6];
    const float* O_w     = (const float*)d_in[7];
    const float* O_b     = (const float*)d_in[8];
    const float* ffn1_w  = (const float*)d_in[9];
    const float* ffn1_b  = (const float*)d_in[10];
    const float* ffn2_w  = (const float*)d_in[11];
    const float* ffn2_b  = (const float*)d_in[12];
    const float* ln1_g   = (const float*)d_in[13];
    const float* ln1_b   = (const float*)d_in[14];
    const float* ln2_g   = (const float*)d_in[15];
    const float* ln2_b   = (const float*)d_in[16];
    const float* final_w = (const float*)d_in[17];
    float* out = (float*)d_out;

    float *ph, *pqkv, *pattn, *pffn, *pcs, *pWf, *pbf;
    cudaGetSymbolAddress((void**)&ph,   g_h);
    cudaGetSymbolAddress((void**)&pqkv, g_qkv);
    cudaGetSymbolAddress((void**)&pattn,g_attn);
    cudaGetSymbolAddress((void**)&pffn, g_ffn);
    cudaGetSymbolAddress((void**)&pcs,  g_cs);
    cudaGetSymbolAddress((void**)&pWf,  g_Wf);
    cudaGetSymbolAddress((void**)&pbf,  g_bf);

    // harness issues ~2 internal launches first; attn as OUR #4 => overall #6 => ncu -s 5 -c 1 target
    freqs_kernel<<<ROWS*16/256, 256>>>(pos, pcs);                                   // 1
    proj_kernel<<<ROWS*64/256, 256>>>(h_in, proj_w, proj_b, ph);                    // 2

    for (int l = 0; l < NLAYER; l++) {
        gemm_h<4,0,0><<<dim3(6,64), 256>>>(ph, qkv_w + (size_t)l*DMODEL*3*DMODEL,   // 3
                                           nullptr, pqkv, ROWS, DMODEL, 3*DMODEL, 0, 0, 0);
        attn_h<<<dim3(SEQ/128, BATCH*NHEAD), 256>>>(pqkv, pcs, pattn);              // 4 <- profiled
        if (l == 0) {
            gemm_h<2,0,0><<<dim3(2,4,4), 256>>>(out_w, O_w, nullptr, pWf,
                                                DMODEL, DMODEL, DMODEL,
                                                DMODEL*DMODEL, DMODEL*DMODEL, DMODEL*DMODEL);
            fuse_bias_kernel<<<NLAYER, 256>>>(out_b, O_w, O_b, pbf);
        }
        gemm_h<2,1,0><<<dim3(2,128), 256>>>(pattn, pWf + (size_t)l*DMODEL*DMODEL,
                                            pbf + l*DMODEL, pffn, ROWS, DMODEL, DMODEL, 0, 0, 0);
        add_ln4<<<ROWS/4, 256>>>(ph, pffn, ln1_g + l*DMODEL, ln1_b + l*DMODEL);
        gemm_h<4,1,1><<<dim3(4,64), 256>>>(ph, ffn1_w + (size_t)l*DMODEL*2*DMODEL,
                                           ffn1_b + l*2*DMODEL, pffn, ROWS, DMODEL, 2*DMODEL, 0, 0, 0);
        gemm_h<2,1,0><<<dim3(2,128), 256>>>(pffn, ffn2_w + (size_t)l*2*DMODEL*DMODEL,
                                            ffn2_b + l*DMODEL, pattn, ROWS, 2*DMODEL, DMODEL, 0, 0, 0);
        add_ln4<<<ROWS/4, 256>>>(ph, pattn, ln2_g + l*DMODEL, ln2_b + l*DMODEL);
    }
    gemm_h<2,0,0><<<dim3(2,128), 256>>>(ph, final_w, nullptr, out, ROWS, DMODEL, DMODEL, 0, 0, 0);
}

// round 9
// speedup vs baseline: 1.4291x; 1.1784x over previous
#include <cuda_runtime.h>
#include <cuda_fp16.h>
#include <math.h>

#define BATCH 4
#define SEQ 2048
#define DMODEL 256
#define NHEAD 8
#define DHEAD 32
#define NLAYER 4
#define ROWS (BATCH*SEQ)   // 8192

// ---------------- scratch ----------------
__device__ float g_h   [ROWS*DMODEL];
__device__ float g_qkv [ROWS*3*DMODEL];
__device__ float g_attn[ROWS*DMODEL];
__device__ float g_ffn [ROWS*2*DMODEL];
__device__ float g_cs  [ROWS*32];
__device__ float g_Wf  [NLAYER*DMODEL*DMODEL];
__device__ float g_bf  [NLAYER*DMODEL];

// ---------------- helpers ----------------
__device__ __forceinline__ unsigned ph2(float a, float b) {
    __half2 h = __floats2half2_rn(a, b);
    return *reinterpret_cast<unsigned*>(&h);
}

__device__ __forceinline__ float ex2(float x) {
    float y; asm("ex2.approx.ftz.f32 %0, %1;" : "=f"(y) : "f"(x)); return y;
}

__device__ __forceinline__ void mma_h(float* d, const unsigned* a, unsigned b0, unsigned b1) {
    asm("mma.sync.aligned.m16n8k16.row.col.f32.f16.f16.f32 "
        "{%0,%1,%2,%3},{%4,%5,%6,%7},{%8,%9},{%0,%1,%2,%3};"
        : "+f"(d[0]), "+f"(d[1]), "+f"(d[2]), "+f"(d[3])
        : "r"(a[0]), "r"(a[1]), "r"(a[2]), "r"(a[3]), "r"(b0), "r"(b1));
}

__device__ __forceinline__ void ldsm4(unsigned* r, const void* p) {
    unsigned a = (unsigned)__cvta_generic_to_shared(p);
    asm volatile("ldmatrix.sync.aligned.m8n8.x4.shared.b16 {%0,%1,%2,%3}, [%4];"
        : "=r"(r[0]), "=r"(r[1]), "=r"(r[2]), "=r"(r[3]) : "r"(a));
}

__device__ __forceinline__ void ldsm4t(unsigned* r, const void* p) {
    unsigned a = (unsigned)__cvta_generic_to_shared(p);
    asm volatile("ldmatrix.sync.aligned.m8n8.x4.trans.shared.b16 {%0,%1,%2,%3}, [%4];"
        : "=r"(r[0]), "=r"(r[1]), "=r"(r[2]), "=r"(r[3]) : "r"(a));
}

// ---------------- small setup kernels ----------------
__global__ void proj_kernel(const float* __restrict__ hin, const float* __restrict__ pw,
                            const float* __restrict__ pb, float* __restrict__ hout) {
    int idx = blockIdx.x*256 + threadIdx.x;       // ROWS*64
    int row = idx >> 6, c4 = idx & 63;
    float4 w = ((const float4*)pw)[c4];
    float4 b = ((const float4*)pb)[c4];
    float hv = hin[row];
    float4 r; r.x = hv*w.x + b.x; r.y = hv*w.y + b.y; r.z = hv*w.z + b.z; r.w = hv*w.w + b.w;
    ((float4*)hout)[row*64 + c4] = r;
}

__global__ void freqs_kernel(const float* __restrict__ pos, float* __restrict__ cs) {
    int idx = blockIdx.x*blockDim.x + threadIdx.x;   // ROWS*16
    int row = idx >> 4; int r = idx & 15; int axis = r >> 3; int fi = r & 7;
    float coord = pos[row*2 + axis];
    float inv = powf(10000.f, -(float)fi * 0.125f);
    float ang = coord * 64.f * inv;
    float s, c; sincosf(ang, &s, &c);
    cs[row*32 + axis*16 + fi]     = c;
    cs[row*32 + axis*16 + 8 + fi] = s;
}

__global__ void fuse_bias_kernel(const float* __restrict__ out_b, const float* __restrict__ O_w,
                                 const float* __restrict__ O_b, float* __restrict__ bf) {
    int l = blockIdx.x, j = threadIdx.x;
    const float* wb = O_w + (size_t)l*DMODEL*DMODEL;
    const float* ob = out_b + l*DMODEL;
    float acc = O_b[l*DMODEL + j];
    for (int i = 0; i < DMODEL; i++) acc = fmaf(ob[i], wb[i*DMODEL + j], acc);
    bf[l*DMODEL + j] = acc;
}

// ---------------- fp16 GEMM: C[M,N] = A[M,K] @ W[K,N] (+bias)(+relu), batched via z ----------------
// BM = MT*32, BN=128, BK=32. 8 warps (2M x 4N). A-frags via ldmatrix.x4.
template<int MT, int HASB, int RELU>
__global__ void __launch_bounds__(256) gemm_h(const float* __restrict__ A, const float* __restrict__ W,
                                              const float* __restrict__ bias, float* __restrict__ C,
                                              int M, int K, int N, int sA, int sW, int sC) {
    __shared__ unsigned As2[2][MT*32*20];
    __shared__ __half  Bsh[2][32*136];
    A += (size_t)blockIdx.z*sA; W += (size_t)blockIdx.z*sW; C += (size_t)blockIdx.z*sC;
    const int BM = MT*32;
    int bm = blockIdx.y*BM, bn = blockIdx.x*128;
    int tid = threadIdx.x, lane = tid & 31, warp = tid >> 5;
    int q = lane >> 2, t = lane & 3;
    int g8 = lane >> 3, il8 = lane & 7;
    int wm = (warp >> 2)*(16*MT), wn = (warp & 3)*32;
    float acc[MT][4][4];
#pragma unroll
    for (int a = 0; a < MT; a++)
#pragma unroll
        for (int b = 0; b < 4; b++)
#pragma unroll
            for (int c = 0; c < 4; c++) acc[a][b][c] = 0.f;

    int arow, acolf;
    if (MT == 4) { arow = tid >> 1; acolf = (tid & 1)*16; }
    else         { arow = tid >> 2; acolf = (tid & 3)*8; }
    int brow = tid >> 4, bcol = (tid & 15)*8;
    const float* Ap = A + (size_t)(bm + arow)*K + acolf;
    const float* Wp = W + (size_t)brow*N + bn + bcol;

    float4 ra[4], rb[4];
    ra[0] = *(const float4*)(Ap);
    ra[1] = *(const float4*)(Ap + 4);
    if (MT == 4) { ra[2] = *(const float4*)(Ap + 8); ra[3] = *(const float4*)(Ap + 12); }
    rb[0] = *(const float4*)(Wp);
    rb[1] = *(const float4*)(Wp + 4);
    rb[2] = *(const float4*)(Wp + (size_t)16*N);
    rb[3] = *(const float4*)(Wp + (size_t)16*N + 4);
    {
        *(uint4*)&As2[0][arow*20 + acolf/2] =
            make_uint4(ph2(ra[0].x,ra[0].y), ph2(ra[0].z,ra[0].w), ph2(ra[1].x,ra[1].y), ph2(ra[1].z,ra[1].w));
        if (MT == 4)
            *(uint4*)&As2[0][arow*20 + acolf/2 + 4] =
                make_uint4(ph2(ra[2].x,ra[2].y), ph2(ra[2].z,ra[2].w), ph2(ra[3].x,ra[3].y), ph2(ra[3].z,ra[3].w));
        *(uint4*)&Bsh[0][brow*136 + bcol] =
            make_uint4(ph2(rb[0].x,rb[0].y), ph2(rb[0].z,rb[0].w), ph2(rb[1].x,rb[1].y), ph2(rb[1].z,rb[1].w));
        *(uint4*)&Bsh[0][(brow+16)*136 + bcol] =
            make_uint4(ph2(rb[2].x,rb[2].y), ph2(rb[2].z,rb[2].w), ph2(rb[3].x,rb[3].y), ph2(rb[3].z,rb[3].w));
    }
    __syncthreads();

    int buf = 0;
    for (int k0 = 0; k0 < K; k0 += 32) {
        bool more = (k0 + 32) < K;
        if (more) {
            ra[0] = *(const float4*)(Ap + k0 + 32);
            ra[1] = *(const float4*)(Ap + k0 + 36);
            if (MT == 4) { ra[2] = *(const float4*)(Ap + k0 + 40); ra[3] = *(const float4*)(Ap + k0 + 44); }
            rb[0] = *(const float4*)(Wp + (size_t)(k0+32)*N);
            rb[1] = *(const float4*)(Wp + (size_t)(k0+32)*N + 4);
            rb[2] = *(const float4*)(Wp + (size_t)(k0+48)*N);
            rb[3] = *(const float4*)(Wp + (size_t)(k0+48)*N + 4);
        }
#pragma unroll
        for (int ks = 0; ks < 2; ks++) {
            unsigned af[MT][4];
#pragma unroll
            for (int mt = 0; mt < MT; mt++)
                ldsm4(af[mt], &As2[buf][(wm + mt*16 + (g8 & 1)*8 + il8)*20 + ks*8 + (g8 >> 1)*4]);
#pragma unroll
            for (int ntp = 0; ntp < 2; ntp++) {
                unsigned bb[4];
                ldsm4t(bb, &Bsh[buf][(ks*16 + (lane & 15))*136 + wn + ntp*16 + (lane >> 4)*8]);
#pragma unroll
                for (int mt = 0; mt < MT; mt++) {
                    mma_h(acc[mt][2*ntp],   af[mt], bb[0], bb[1]);
                    mma_h(acc[mt][2*ntp+1], af[mt], bb[2], bb[3]);
                }
            }
        }
        if (more) {
            int nb = buf ^ 1;
            *(uint4*)&As2[nb][arow*20 + acolf/2] =
                make_uint4(ph2(ra[0].x,ra[0].y), ph2(ra[0].z,ra[0].w), ph2(ra[1].x,ra[1].y), ph2(ra[1].z,ra[1].w));
            if (MT == 4)
                *(uint4*)&As2[nb][arow*20 + acolf/2 + 4] =
                    make_uint4(ph2(ra[2].x,ra[2].y), ph2(ra[2].z,ra[2].w), ph2(ra[3].x,ra[3].y), ph2(ra[3].z,ra[3].w));
            *(uint4*)&Bsh[nb][brow*136 + bcol] =
                make_uint4(ph2(rb[0].x,rb[0].y), ph2(rb[0].z,rb[0].w), ph2(rb[1].x,rb[1].y), ph2(rb[1].z,rb[1].w));
            *(uint4*)&Bsh[nb][(brow+16)*136 + bcol] =
                make_uint4(ph2(rb[2].x,rb[2].y), ph2(rb[2].z,rb[2].w), ph2(rb[3].x,rb[3].y), ph2(rb[3].z,rb[3].w));
        }
        __syncthreads();
        buf ^= 1;
    }

#pragma unroll
    for (int mt = 0; mt < MT; mt++) {
        int r0 = bm + wm + mt*16 + q;
#pragma unroll
        for (int nt = 0; nt < 4; nt++) {
            int c0 = bn + wn + nt*8 + 2*t;
            float b0 = 0.f, b1 = 0.f;
            if (HASB) { b0 = bias[c0]; b1 = bias[c0+1]; }
            float v0 = acc[mt][nt][0] + b0, v1 = acc[mt][nt][1] + b1;
            float v2 = acc[mt][nt][2] + b0, v3 = acc[mt][nt][3] + b1;
            if (RELU) { v0=fmaxf(v0,0.f); v1=fmaxf(v1,0.f); v2=fmaxf(v2,0.f); v3=fmaxf(v3,0.f); }
            float2 w0; w0.x = v0; w0.y = v1;
            float2 w1; w1.x = v2; w1.y = v3;
            *(float2*)&C[(size_t)r0*N + c0]     = w0;
            *(float2*)&C[(size_t)(r0+8)*N + c0] = w1;
        }
    }
}

// ---------------- fp16 flash attention: fused rope, base-2 softmax, P in registers ----------------
// Block = (b,h,128 q rows), 8 warps, 64-key chunks.
// K B-frags via ldmatrix.x4 (non-trans), V via ldmatrix.x4.trans, P never leaves registers.
__global__ void __launch_bounds__(256) attn_h(const float* __restrict__ qkv,
                                              const float* __restrict__ cs,
                                              float* __restrict__ out) {
    __shared__ unsigned Q2[128*20];
    __shared__ unsigned K2[64*20];
    __shared__ __half  Vh[64*40];

    int bh = blockIdx.y; int b = bh >> 3; int h = bh & 7;
    int qbase = blockIdx.x * 128;
    int tid = threadIdx.x, lane = tid & 31, w = tid >> 5;
    int q = lane >> 2, t = lane & 3;
    int g8 = lane >> 3, il8 = lane & 7;
    const float* base = qkv + (size_t)b*SEQ*768;
    const float scale2 = 0.25503472f;  // (1/sqrt(32)) * log2(e), folded into Q

    // ---- load Q tile 128x32 with rope + scale ----
    {
        int r = tid >> 1, c = (tid & 1)*16;
        int grow = qbase + r;
        const float* src = base + (size_t)grow*768 + h*DHEAD + c;
        float v[16];
        *(float4*)&v[0]  = *(const float4*)(src);
        *(float4*)&v[4]  = *(const float4*)(src + 4);
        *(float4*)&v[8]  = *(const float4*)(src + 8);
        *(float4*)&v[12] = *(const float4*)(src + 12);
        const float* cr = cs + (size_t)(b*SEQ + grow)*32 + (c >> 4)*16;
        float rv[16];
#pragma unroll
        for (int i = 0; i < 8; i++) {
            float co = cr[i], si = cr[8+i];
            rv[i]   = (v[i]*co - v[i+8]*si)*scale2;
            rv[i+8] = (v[i+8]*co + v[i]*si)*scale2;
        }
        *(uint4*)&Q2[r*20 + c/2] =
            make_uint4(ph2(rv[0],rv[1]), ph2(rv[2],rv[3]), ph2(rv[4],rv[5]), ph2(rv[6],rv[7]));
        *(uint4*)&Q2[r*20 + c/2 + 4] =
            make_uint4(ph2(rv[8],rv[9]), ph2(rv[10],rv[11]), ph2(rv[12],rv[13]), ph2(rv[14],rv[15]));
    }
    __syncthreads();

    unsigned qf[2][4];
#pragma unroll
    for (int ks = 0; ks < 2; ks++)
        ldsm4(qf[ks], &Q2[(w*16 + (g8 & 1)*8 + il8)*20 + ks*8 + (g8 >> 1)*4]);

    float accO[4][4] = {};
    float m0 = -1e30f, m1 = -1e30f, l0 = 0.f, l1 = 0.f;

    // K/V loader: warps 0-3 load K (with rope), warps 4-7 load V
    int isV = tid >> 7;
    int t2 = tid & 127;
    int kr = t2 >> 1, c = (t2 & 1)*16;
    const float* kvsrc = base + (size_t)kr*768 + (isV ? 2*DMODEL : DMODEL) + h*DHEAD + c;
    const float* csrc  = cs + (size_t)(b*SEQ + kr)*32 + (c >> 4)*16;

    float pv[16], pc[16];
    *(float4*)&pv[0]  = *(const float4*)(kvsrc);
    *(float4*)&pv[4]  = *(const float4*)(kvsrc + 4);
    *(float4*)&pv[8]  = *(const float4*)(kvsrc + 8);
    *(float4*)&pv[12] = *(const float4*)(kvsrc + 12);
    if (!isV) {
        *(float4*)&pc[0]  = *(const float4*)(csrc);
        *(float4*)&pc[4]  = *(const float4*)(csrc + 4);
        *(float4*)&pc[8]  = *(const float4*)(csrc + 8);
        *(float4*)&pc[12] = *(const float4*)(csrc + 12);
    }

    for (int kc0 = 0; kc0 < SEQ; kc0 += 64) {
        // commit prefetched chunk
        if (!isV) {
            float rv[16];
#pragma unroll
            for (int i = 0; i < 8; i++) {
                float co = pc[i], si = pc[8+i];
                rv[i]   = pv[i]*co - pv[i+8]*si;
                rv[i+8] = pv[i+8]*co + pv[i]*si;
            }
            *(uint4*)&K2[kr*20 + c/2] =
                make_uint4(ph2(rv[0],rv[1]), ph2(rv[2],rv[3]), ph2(rv[4],rv[5]), ph2(rv[6],rv[7]));
            *(uint4*)&K2[kr*20 + c/2 + 4] =
                make_uint4(ph2(rv[8],rv[9]), ph2(rv[10],rv[11]), ph2(rv[12],rv[13]), ph2(rv[14],rv[15]));
        } else {
            *(uint4*)&Vh[kr*40 + c] =
                make_uint4(ph2(pv[0],pv[1]), ph2(pv[2],pv[3]), ph2(pv[4],pv[5]), ph2(pv[6],pv[7]));
            *(uint4*)&Vh[kr*40 + c + 8] =
                make_uint4(ph2(pv[8],pv[9]), ph2(pv[10],pv[11]), ph2(pv[12],pv[13]), ph2(pv[14],pv[15]));
        }
        __syncthreads();

        // prefetch next chunk
        if (kc0 + 64 < SEQ) {
            const float* ns = kvsrc + (size_t)(kc0 + 64)*768;
            *(float4*)&pv[0]  = *(const float4*)(ns);
            *(float4*)&pv[4]  = *(const float4*)(ns + 4);
            *(float4*)&pv[8]  = *(const float4*)(ns + 8);
            *(float4*)&pv[12] = *(const float4*)(ns + 12);
            if (!isV) {
                const float* nc = csrc + (size_t)(kc0 + 64)*32;
                *(float4*)&pc[0]  = *(const float4*)(nc);
                *(float4*)&pc[4]  = *(const float4*)(nc + 4);
                *(float4*)&pc[8]  = *(const float4*)(nc + 8);
                *(float4*)&pc[12] = *(const float4*)(nc + 12);
            }
        }

        // S = Q @ K^T : m16 x n64 x k32; K B-frags via ldmatrix.x4 (1 per 2 MMAs)
        float s[8][4] = {};
#pragma unroll
        for (int ks = 0; ks < 2; ks++) {
#pragma unroll
            for (int ntp = 0; ntp < 4; ntp++) {
                unsigned kb[4];
                ldsm4(kb, &K2[(ntp*16 + ((g8 >> 1) & 1)*8 + il8)*20 + ks*8 + (g8 & 1)*4]);
                mma_h(s[2*ntp],   qf[ks], kb[0], kb[1]);
                mma_h(s[2*ntp+1], qf[ks], kb[2], kb[3]);
            }
        }

        // online softmax (base 2)
        float rm0 = -1e30f, rm1 = -1e30f;
#pragma unroll
        for (int nt = 0; nt < 8; nt++) {
            rm0 = fmaxf(rm0, fmaxf(s[nt][0], s[nt][1]));
            rm1 = fmaxf(rm1, fmaxf(s[nt][2], s[nt][3]));
        }
        rm0 = fmaxf(rm0, __shfl_xor_sync(0xffffffffu, rm0, 1));
        rm0 = fmaxf(rm0, __shfl_xor_sync(0xffffffffu, rm0, 2));
        rm1 = fmaxf(rm1, __shfl_xor_sync(0xffffffffu, rm1, 1));
        rm1 = fmaxf(rm1, __shfl_xor_sync(0xffffffffu, rm1, 2));
        float mn0 = fmaxf(m0, rm0), mn1 = fmaxf(m1, rm1);
        float cf0 = ex2(m0 - mn0), cf1 = ex2(m1 - mn1);
        m0 = mn0; m1 = mn1;
        float rs0 = 0.f, rs1 = 0.f;
#pragma unroll
        for (int nt = 0; nt < 8; nt++) {
            s[nt][0] = ex2(s[nt][0] - mn0);
            s[nt][1] = ex2(s[nt][1] - mn0);
            s[nt][2] = ex2(s[nt][2] - mn1);
            s[nt][3] = ex2(s[nt][3] - mn1);
            rs0 += s[nt][0] + s[nt][1];
            rs1 += s[nt][2] + s[nt][3];
        }
        rs0 += __shfl_xor_sync(0xffffffffu, rs0, 1);
        rs0 += __shfl_xor_sync(0xffffffffu, rs0, 2);
        rs1 += __shfl_xor_sync(0xffffffffu, rs1, 1);
        rs1 += __shfl_xor_sync(0xffffffffu, rs1, 2);
        l0 = l0*cf0 + rs0; l1 = l1*cf1 + rs1;
#pragma unroll
        for (int nt = 0; nt < 4; nt++) {
            accO[nt][0] *= cf0; accO[nt][1] *= cf0;
            accO[nt][2] *= cf1; accO[nt][3] *= cf1;
        }

        // O += P @ V : P stays in registers (C-frag of S == A-frag of PV)
#pragma unroll
        for (int ks = 0; ks < 4; ks++) {
            unsigned pa[4];
            pa[0] = ph2(s[2*ks][0],   s[2*ks][1]);
            pa[1] = ph2(s[2*ks][2],   s[2*ks][3]);
            pa[2] = ph2(s[2*ks+1][0], s[2*ks+1][1]);
            pa[3] = ph2(s[2*ks+1][2], s[2*ks+1][3]);
#pragma unroll
            for (int ntp = 0; ntp < 2; ntp++) {
                unsigned bbv[4];
                ldsm4t(bbv, &Vh[(ks*16 + (lane & 15))*40 + ntp*16 + (lane >> 4)*8]);
                mma_h(accO[2*ntp],   pa, bbv[0], bbv[1]);
                mma_h(accO[2*ntp+1], pa, bbv[2], bbv[3]);
            }
        }
        __syncthreads();
    }

    // epilogue
    float il0 = 1.f/l0, il1 = 1.f/l1;
    int qr = qbase + w*16 + q;
#pragma unroll
    for (int nt = 0; nt < 4; nt++) {
        int cc = h*DHEAD + nt*8 + 2*t;
        float2 v0; v0.x = accO[nt][0]*il0; v0.y = accO[nt][1]*il0;
        float2 v1; v1.x = accO[nt][2]*il1; v1.y = accO[nt][3]*il1;
        *(float2*)&out[(size_t)(b*SEQ + qr)*DMODEL + cc]     = v0;
        *(float2*)&out[(size_t)(b*SEQ + qr + 8)*DMODEL + cc] = v1;
    }
}

// ---------------- residual add + layernorm: 4 rows/block, float4/thread ----------------
__global__ void add_ln4(float* __restrict__ h, const float* __restrict__ o,
                        const float* __restrict__ g, const float* __restrict__ bb) {
    __shared__ float red[16];
    int tid = threadIdx.x;
    int row = blockIdx.x*4 + (tid >> 6);
    int c4 = tid & 63;
    int lane = tid & 31, warp = tid >> 5;
    float4 hv = ((const float4*)h)[row*64 + c4];
    float4 ov = ((const float4*)o)[row*64 + c4];
    float x0 = hv.x + ov.x, x1 = hv.y + ov.y, x2 = hv.z + ov.z, x3 = hv.w + ov.w;
    float s1 = x0 + x1 + x2 + x3;
    float s2 = x0*x0 + x1*x1 + x2*x2 + x3*x3;
#pragma unroll
    for (int off = 16; off; off >>= 1) {
        s1 += __shfl_xor_sync(0xffffffffu, s1, off);
        s2 += __shfl_xor_sync(0xffffffffu, s2, off);
    }
    if (lane == 0) { red[warp] = s1; red[8 + warp] = s2; }
    __syncthreads();
    int wp = warp & ~1;
    float t1 = red[wp] + red[wp+1];
    float t2 = red[8+wp] + red[8+wp+1];
    float m = t1 * (1.f/DMODEL);
    float var = t2 * (1.f/DMODEL) - m*m;
    float rs = rsqrtf(var + 1e-5f);
    float4 gv = ((const float4*)g)[c4];
    float4 bv = ((const float4*)bb)[c4];
    float4 y;
    y.x = (x0 - m)*rs*gv.x + bv.x;
    y.y = (x1 - m)*rs*gv.y + bv.y;
    y.z = (x2 - m)*rs*gv.z + bv.z;
    y.w = (x3 - m)*rs*gv.w + bv.w;
    ((float4*)h)[row*64 + c4] = y;
}

// ---------------- host ----------------
extern "C" void kernel_launch(void* const* d_in, const int* in_sizes, int n_in,
                              void* d_out, int out_size) {
    const float* h_in    = (const float*)d_in[0];
    const float* pos     = (const float*)d_in[1];
    const float* proj_w  = (const float*)d_in[2];
    const float* proj_b  = (const float*)d_in[3];
    const float* qkv_w   = (const float*)d_in[4];
    const float* out_w   = (const float*)d_in[5];
    const float* out_b   = (const float*)d_in[6];
    const float* O_w     = (const float*)d_in[7];
    const float* O_b     = (const float*)d_in[8];
    const float* ffn1_w  = (const float*)d_in[9];
    const float* ffn1_b  = (const float*)d_in[10];
    const float* ffn2_w  = (const float*)d_in[11];
    const float* ffn2_b  = (const float*)d_in[12];
    const float* ln1_g   = (const float*)d_in[13];
    const float* ln1_b   = (const float*)d_in[14];
    const float* ln2_g   = (const float*)d_in[15];
    const float* ln2_b   = (const float*)d_in[16];
    const float* final_w = (const float*)d_in[17];
    float* out = (float*)d_out;

    float *ph, *pqkv, *pattn, *pffn, *pcs, *pWf, *pbf;
    cudaGetSymbolAddress((void**)&ph,   g_h);
    cudaGetSymbolAddress((void**)&pqkv, g_qkv);
    cudaGetSymbolAddress((void**)&pattn,g_attn);
    cudaGetSymbolAddress((void**)&pffn, g_ffn);
    cudaGetSymbolAddress((void**)&pcs,  g_cs);
    cudaGetSymbolAddress((void**)&pWf,  g_Wf);
    cudaGetSymbolAddress((void**)&pbf,  g_bf);

    // attn as OUR #4 => overall launch #6 => ncu -s 5 -c 1 target
    freqs_kernel<<<ROWS*16/256, 256>>>(pos, pcs);                                   // 1
    proj_kernel<<<ROWS*64/256, 256>>>(h_in, proj_w, proj_b, ph);                    // 2

    for (int l = 0; l < NLAYER; l++) {
        gemm_h<4,0,0><<<dim3(6,64), 256>>>(ph, qkv_w + (size_t)l*DMODEL*3*DMODEL,   // 3
                                           nullptr, pqkv, ROWS, DMODEL, 3*DMODEL, 0, 0, 0);
        attn_h<<<dim3(SEQ/128, BATCH*NHEAD), 256>>>(pqkv, pcs, pattn);              // 4 <- profiled
        if (l == 0) {
            gemm_h<2,0,0><<<dim3(2,4,4), 256>>>(out_w, O_w, nullptr, pWf,
                                                DMODEL, DMODEL, DMODEL,
                                                DMODEL*DMODEL, DMODEL*DMODEL, DMODEL*DMODEL);
            fuse_bias_kernel<<<NLAYER, 256>>>(out_b, O_w, O_b, pbf);
        }
        gemm_h<2,1,0><<<dim3(2,128), 256>>>(pattn, pWf + (size_t)l*DMODEL*DMODEL,
                                            pbf + l*DMODEL, pffn, ROWS, DMODEL, DMODEL, 0, 0, 0);
        add_ln4<<<ROWS/4, 256>>>(ph, pffn, ln1_g + l*DMODEL, ln1_b + l*DMODEL);
        gemm_h<4,1,1><<<dim3(4,64), 256>>>(ph, ffn1_w + (size_t)l*DMODEL*2*DMODEL,
                                           ffn1_b + l*2*DMODEL, pffn, ROWS, DMODEL, 2*DMODEL, 0, 0, 0);
        gemm_h<2,1,0><<<dim3(2,128), 256>>>(pffn, ffn2_w + (size_t)l*2*DMODEL*DMODEL,
                                            ffn2_b + l*DMODEL, pattn, ROWS, 2*DMODEL, DMODEL, 0, 0, 0);
        add_ln4<<<ROWS/4, 256>>>(ph, pattn, ln2_g + l*DMODEL, ln2_b + l*DMODEL);
    }
    gemm_h<2,0,0><<<dim3(2,128), 256>>>(ph, final_w, nullptr, out, ROWS, DMODEL, DMODEL, 0, 0, 0);
}